// round 1
// baseline (speedup 1.0000x reference)
#include <cuda_runtime.h>
#include <math.h>

// ---------------------------------------------------------------------------
// LabelSmoothing KL-div loss, reduced to a per-row streaming sum + 2 gathers:
//   contrib(row) = C - eps*(rowsum - pred[row][0]) - (0.9 - eps)*pred[row][tgt]
//   (0 if tgt == PAD_IDX)
// where eps = SMOOTHING/(V-2), C = (V-2)*eps*ln(eps) + (1-S)*ln(1-S).
// HBM-bound: 262 MB read.
// ---------------------------------------------------------------------------

#define PAD_IDX 0

__device__ int    g_is64;              // 1 if target buffer is int64-layout
__device__ double g_partials[65536];   // per-row contributions (N <= 65536)

// ---------------------------------------------------------------------------
// Detect whether the target buffer holds int64 or int32 values.
// Reading the first N int32 words is safe under either layout (int64 layout
// has 2N words, int32 layout has exactly N). In int64 little-endian layout,
// odd words are the high halves of the first N/2 targets -> all zero.
// In int32 layout odd words are random targets in [0, V) -> essentially
// impossible to all be zero.
// ---------------------------------------------------------------------------
__global__ void detect_dtype_kernel(const int* __restrict__ t32, int N)
{
    __shared__ int any_nonzero;
    if (threadIdx.x == 0) any_nonzero = 0;
    __syncthreads();
    for (int i = 1 + 2 * (int)threadIdx.x; i < N; i += 2 * (int)blockDim.x) {
        if (t32[i] != 0) any_nonzero = 1;   // benign race: all writers store 1
    }
    __syncthreads();
    if (threadIdx.x == 0) g_is64 = (any_nonzero ? 0 : 1);
}

// ---------------------------------------------------------------------------
// One block per row: coalesced float4 streaming sum of V log-probs,
// then thread 0 assembles the analytic row contribution.
// ---------------------------------------------------------------------------
__global__ __launch_bounds__(512) void row_kernel(
    const float* __restrict__ pred,
    const void*  __restrict__ tgt_raw,
    int V, double eps, double coefC, double w_tgt)
{
    const int row = blockIdx.x;
    const float* __restrict__ p = pred + (size_t)row * (size_t)V;

    // ---- streaming row sum (vectorized, coalesced) ----
    float local = 0.0f;
    const int nv4 = V >> 2;
    const float4* __restrict__ p4 = (const float4*)p;
    #pragma unroll 4
    for (int i = threadIdx.x; i < nv4; i += blockDim.x) {
        float4 v = p4[i];
        local += (v.x + v.y) + (v.z + v.w);
    }
    for (int i = (nv4 << 2) + threadIdx.x; i < V; i += blockDim.x)
        local += p[i];

    // ---- warp + block reduction ----
    #pragma unroll
    for (int o = 16; o > 0; o >>= 1)
        local += __shfl_xor_sync(0xffffffffu, local, o);

    __shared__ float warpsum[16];
    const int wid = threadIdx.x >> 5;
    const int lid = threadIdx.x & 31;
    if (lid == 0) warpsum[wid] = local;
    __syncthreads();

    if (threadIdx.x == 0) {
        float s = 0.0f;
        const int nw = (blockDim.x + 31) >> 5;
        for (int i = 0; i < nw; i++) s += warpsum[i];

        long long t;
        if (g_is64) t = ((const long long*)tgt_raw)[row];
        else        t = (long long)((const int*)tgt_raw)[row];

        double out = 0.0;
        if (t != PAD_IDX && t >= 0 && t < (long long)V) {
            const double rowsum_excl0 = (double)s - (double)p[0];
            const double ptgt = (double)p[t];
            out = coefC - eps * rowsum_excl0 - w_tgt * ptgt;
        }
        g_partials[row] = out;
    }
}

// ---------------------------------------------------------------------------
// Sum the N per-row doubles into the scalar float output.
// ---------------------------------------------------------------------------
__global__ __launch_bounds__(256) void final_kernel(float* __restrict__ out, int N)
{
    double local = 0.0;
    for (int i = threadIdx.x; i < N; i += blockDim.x)
        local += g_partials[i];

    #pragma unroll
    for (int o = 16; o > 0; o >>= 1)
        local += __shfl_xor_sync(0xffffffffu, local, o);

    __shared__ double ws[8];
    const int wid = threadIdx.x >> 5;
    const int lid = threadIdx.x & 31;
    if (lid == 0) ws[wid] = local;
    __syncthreads();

    if (threadIdx.x == 0) {
        double total = 0.0;
        const int nw = (blockDim.x + 31) >> 5;
        for (int i = 0; i < nw; i++) total += ws[i];
        out[0] = (float)total;
    }
}

extern "C" void kernel_launch(void* const* d_in, const int* in_sizes, int n_in,
                              void* d_out, int out_size)
{
    const float* pred = (const float*)d_in[0];
    const void*  tgt  = d_in[1];

    const int total = in_sizes[0];   // B*S*V
    const int N     = in_sizes[1];   // B*S rows
    const int V     = total / N;

    const double smoothing = 0.1;
    const double eps   = smoothing / (double)(V - 2);
    const double coefC = (double)(V - 2) * eps * log(eps)
                       + (1.0 - smoothing) * log(1.0 - smoothing);
    const double w_tgt = (1.0 - smoothing) - eps;

    detect_dtype_kernel<<<1, 256>>>((const int*)tgt, N);
    row_kernel<<<N, 512>>>(pred, tgt, V, eps, coefC, w_tgt);
    final_kernel<<<1, 256>>>((float*)d_out, N);
}